// round 3
// baseline (speedup 1.0000x reference)
#include <cuda_runtime.h>
#include <cuda_bf16.h>
#include <mma.h>
using namespace nvcuda;

#define T  1024
#define HD 2048
#define ID 4096
#define E  8

#define BM 128
#define BN 64
#define BK 32
#define APITCH 40   // bf16 elements; 80B row, multiple of 16B
#define BPITCH 72   // bf16 elements; 144B row, multiple of 16B
#define CPITCH 68   // f32 elements; 272B row, multiple of 16B

// ---- scratch (static device globals; allocation-free per harness rules) ----
__device__ float g_h_shared[(size_t)T * ID];
__device__ float g_h_routed[(size_t)(T + E * BM) * ID];  // per-expert 128-row pad
__device__ int   g_expert[T];
__device__ float g_score[T];
__device__ int   g_perm[T];
__device__ int   g_offsets[E + 1];

__device__ __forceinline__ void split_bf16(float v, __nv_bfloat16& h, __nv_bfloat16& l) {
    h = __float2bfloat16_rn(v);
    l = __float2bfloat16_rn(v - __bfloat162float(h));
}

// ============================================================================
// Router: one warp per token; argmax (first-max tie-break) + sigmoid score.
// ============================================================================
__global__ void router_kernel(const float* __restrict__ x,
                              const float* __restrict__ wr) {
    int warp = (blockIdx.x * blockDim.x + threadIdx.x) >> 5;
    int lane = threadIdx.x & 31;
    if (warp >= T) return;
    const float* xr = x + (size_t)warp * HD;
    float acc[E];
#pragma unroll
    for (int e = 0; e < E; e++) acc[e] = 0.f;
    for (int h = lane; h < HD; h += 32) {
        float xv = xr[h];
        const float* w = wr + (size_t)h * E;
#pragma unroll
        for (int e = 0; e < E; e++) acc[e] += xv * w[e];
    }
#pragma unroll
    for (int e = 0; e < E; e++) {
#pragma unroll
        for (int o = 16; o; o >>= 1) acc[e] += __shfl_xor_sync(0xffffffffu, acc[e], o);
    }
    if (lane == 0) {
        int best = 0; float bv = acc[0];
#pragma unroll
        for (int e = 1; e < E; e++) if (acc[e] > bv) { bv = acc[e]; best = e; }
        g_expert[warp] = best;
        g_score[warp]  = 1.f / (1.f + __expf(-bv));
    }
}

// ============================================================================
// Histogram + scan + permutation (single block). Output is invariant to the
// atomic-dependent intra-expert order (rows scattered back by token id).
// ============================================================================
__global__ void perm_kernel() {
    __shared__ int cnt[E];
    __shared__ int off[E + 1];
    __shared__ int cur[E];
    int t = threadIdx.x;
    if (t < E) cnt[t] = 0;
    __syncthreads();
    int e = g_expert[t];
    atomicAdd(&cnt[e], 1);
    __syncthreads();
    if (t == 0) {
        off[0] = 0;
        for (int i = 0; i < E; i++) off[i + 1] = off[i] + cnt[i];
    }
    __syncthreads();
    if (t < E) cur[t] = off[t];
    __syncthreads();
    int pos = atomicAdd(&cur[e], 1);
    g_perm[pos] = t;
    if (t <= E) g_offsets[t] = off[t];
}

// ============================================================================
// GEMM1 (wmma, split-bf16): h = silu(Xs@Wg) * (Xs@Wu)
// Block tile 128x64xK, 8 warps (4x2), warp tile 32x32 for each of gate/up.
// Split into hi/lo bf16 during global->smem staging; 3 MMAs per product.
// Routed scratch rows use per-expert padded base; pad rows are exact zeros.
// ============================================================================
__global__ __launch_bounds__(256)
void gateup_kernel(const float* __restrict__ X,
                   const float* __restrict__ Wg,
                   const float* __restrict__ Wu,
                   int routed) {
    __shared__ __nv_bfloat16 Ah[BM][APITCH], Al[BM][APITCH];
    __shared__ __nv_bfloat16 Bgh[BK][BPITCH], Bgl[BK][BPITCH];
    __shared__ __nv_bfloat16 Buh[BK][BPITCH], Bul[BK][BPITCH];
    __shared__ int   s_tok[BM];
    __shared__ float s_scl[BM];

    int tid = threadIdx.x;
    int obase, cnt, pbase;
    const float *wg, *wu;
    float* Hout;
    if (routed) {
        int e = blockIdx.z;
        obase = g_offsets[e];
        cnt   = g_offsets[e + 1] - obase;
        pbase = obase + e * BM;
        wg = Wg + (size_t)e * HD * ID;
        wu = Wu + (size_t)e * HD * ID;
        Hout = g_h_routed;
    } else {
        obase = 0; cnt = T; pbase = 0; wg = Wg; wu = Wu; Hout = g_h_shared;
    }
    int m0 = blockIdx.y * BM;
    if (m0 >= cnt) return;
    int n0 = blockIdx.x * BN;

    if (tid < BM) {
        int gr = m0 + tid;
        int tok = 0; float sc = 0.f;
        if (gr < cnt) {
            if (routed) { tok = g_perm[obase + gr]; sc = g_score[tok]; }
            else        { tok = gr;                 sc = 1.f; }
        }
        s_tok[tid] = tok; s_scl[tid] = sc;
    }
    __syncthreads();

    int warp = tid >> 5;
    int wm0 = (warp >> 1) * 32;
    int wn0 = (warp & 1) * 32;

    wmma::fragment<wmma::accumulator, 16, 16, 16, float> accg[2][2], accu[2][2];
#pragma unroll
    for (int mi = 0; mi < 2; mi++)
#pragma unroll
        for (int ni = 0; ni < 2; ni++) {
            wmma::fill_fragment(accg[mi][ni], 0.f);
            wmma::fill_fragment(accu[mi][ni], 0.f);
        }

    int ar = tid & 127;          // A row
    int ak = (tid >> 7) * 16;    // A k-base (0 or 16)

    for (int kt = 0; kt < HD; kt += BK) {
        // ---- stage A (gather + scale + split) ----
        {
            float sc = s_scl[ar];
            const float* xp = X + (size_t)s_tok[ar] * HD + kt + ak;
#pragma unroll
            for (int i = 0; i < 4; i++) {
                float4 v = make_float4(0.f, 0.f, 0.f, 0.f);
                if (sc != 0.f) {
                    v = *(const float4*)(xp + i * 4);
                    v.x *= sc; v.y *= sc; v.z *= sc; v.w *= sc;
                }
                int c = ak + i * 4;
                split_bf16(v.x, Ah[ar][c + 0], Al[ar][c + 0]);
                split_bf16(v.y, Ah[ar][c + 1], Al[ar][c + 1]);
                split_bf16(v.z, Ah[ar][c + 2], Al[ar][c + 2]);
                split_bf16(v.w, Ah[ar][c + 3], Al[ar][c + 3]);
            }
        }
        // ---- stage B (gate + up, split) ----
#pragma unroll
        for (int i = 0; i < 2; i++) {
            int idx = tid * 2 + i;        // 0..511
            int kr  = idx >> 4;           // 0..31
            int c4  = (idx & 15) * 4;     // 0..60
            float4 vg = *(const float4*)(wg + (size_t)(kt + kr) * ID + n0 + c4);
            float4 vu = *(const float4*)(wu + (size_t)(kt + kr) * ID + n0 + c4);
            split_bf16(vg.x, Bgh[kr][c4 + 0], Bgl[kr][c4 + 0]);
            split_bf16(vg.y, Bgh[kr][c4 + 1], Bgl[kr][c4 + 1]);
            split_bf16(vg.z, Bgh[kr][c4 + 2], Bgl[kr][c4 + 2]);
            split_bf16(vg.w, Bgh[kr][c4 + 3], Bgl[kr][c4 + 3]);
            split_bf16(vu.x, Buh[kr][c4 + 0], Bul[kr][c4 + 0]);
            split_bf16(vu.y, Buh[kr][c4 + 1], Bul[kr][c4 + 1]);
            split_bf16(vu.z, Buh[kr][c4 + 2], Bul[kr][c4 + 2]);
            split_bf16(vu.w, Buh[kr][c4 + 3], Bul[kr][c4 + 3]);
        }
        __syncthreads();

#pragma unroll
        for (int kk = 0; kk < BK; kk += 16) {
            wmma::fragment<wmma::matrix_a, 16, 16, 16, __nv_bfloat16, wmma::row_major> ah[2], al[2];
#pragma unroll
            for (int mi = 0; mi < 2; mi++) {
                wmma::load_matrix_sync(ah[mi], &Ah[wm0 + mi * 16][kk], APITCH);
                wmma::load_matrix_sync(al[mi], &Al[wm0 + mi * 16][kk], APITCH);
            }
            wmma::fragment<wmma::matrix_b, 16, 16, 16, __nv_bfloat16, wmma::row_major> bgh[2], bgl[2], buh[2], bul[2];
#pragma unroll
            for (int ni = 0; ni < 2; ni++) {
                wmma::load_matrix_sync(bgh[ni], &Bgh[kk][wn0 + ni * 16], BPITCH);
                wmma::load_matrix_sync(bgl[ni], &Bgl[kk][wn0 + ni * 16], BPITCH);
                wmma::load_matrix_sync(buh[ni], &Buh[kk][wn0 + ni * 16], BPITCH);
                wmma::load_matrix_sync(bul[ni], &Bul[kk][wn0 + ni * 16], BPITCH);
            }
#pragma unroll
            for (int mi = 0; mi < 2; mi++)
#pragma unroll
                for (int ni = 0; ni < 2; ni++) {
                    wmma::mma_sync(accg[mi][ni], ah[mi], bgh[ni], accg[mi][ni]);
                    wmma::mma_sync(accg[mi][ni], ah[mi], bgl[ni], accg[mi][ni]);
                    wmma::mma_sync(accg[mi][ni], al[mi], bgh[ni], accg[mi][ni]);
                    wmma::mma_sync(accu[mi][ni], ah[mi], buh[ni], accu[mi][ni]);
                    wmma::mma_sync(accu[mi][ni], ah[mi], bul[ni], accu[mi][ni]);
                    wmma::mma_sync(accu[mi][ni], al[mi], buh[ni], accu[mi][ni]);
                }
        }
        __syncthreads();
    }

    // epilogue: h = silu(g) * u, written as full tiles (pad rows are zeros)
#pragma unroll
    for (int mi = 0; mi < 2; mi++)
#pragma unroll
        for (int ni = 0; ni < 2; ni++) {
            wmma::fragment<wmma::accumulator, 16, 16, 16, float> hf;
#pragma unroll
            for (int i = 0; i < hf.num_elements; i++) {
                float g = accg[mi][ni].x[i];
                hf.x[i] = (g / (1.f + __expf(-g))) * accu[mi][ni].x[i];
            }
            wmma::store_matrix_sync(
                Hout + (size_t)(pbase + m0 + wm0 + mi * 16) * ID + n0 + wn0 + ni * 16,
                hf, ID, wmma::mem_row_major);
        }
}

// ============================================================================
// GEMM2 (wmma, split-bf16): down projection with smem-staged scatter epilogue.
//   routed=0: out[t]        = h_shared[t] @ ws_down     (writes all of out)
//   routed=1: out[perm[p]] += h_routed[p] @ we_down[e]  (after shared pass)
// ============================================================================
__global__ __launch_bounds__(256)
void down_kernel(const float* __restrict__ Wd,
                 float* __restrict__ out,
                 int routed) {
    // overlay: [A hi/lo bf16 | B hi/lo bf16] during mainloop, C f32 in epilogue
    __shared__ __align__(16) char smem_raw[BM * CPITCH * 4];  // 34816 B (largest)
    __nv_bfloat16* Ah = (__nv_bfloat16*)smem_raw;             // [BM][APITCH]
    __nv_bfloat16* Al = Ah + BM * APITCH;
    __nv_bfloat16* Bh = Al + BM * APITCH;                     // [BK][BPITCH]
    __nv_bfloat16* Bl = Bh + BK * BPITCH;
    float* Cs = (float*)smem_raw;                             // [BM][CPITCH]

    int tid = threadIdx.x;
    int obase, cnt, pbase;
    const float* wd;
    const float* Hin;
    if (routed) {
        int e = blockIdx.z;
        obase = g_offsets[e];
        cnt   = g_offsets[e + 1] - obase;
        pbase = obase + e * BM;
        wd  = Wd + (size_t)e * ID * HD;
        Hin = g_h_routed;
    } else {
        obase = 0; cnt = T; pbase = 0; wd = Wd; Hin = g_h_shared;
    }
    int m0 = blockIdx.y * BM;
    if (m0 >= cnt) return;
    int n0 = blockIdx.x * BN;

    int warp = tid >> 5;
    int wm0 = (warp >> 1) * 32;
    int wn0 = (warp & 1) * 32;

    wmma::fragment<wmma::accumulator, 16, 16, 16, float> acc[2][2];
#pragma unroll
    for (int mi = 0; mi < 2; mi++)
#pragma unroll
        for (int ni = 0; ni < 2; ni++) wmma::fill_fragment(acc[mi][ni], 0.f);

    int ar = tid & 127;
    int ak = (tid >> 7) * 16;

    for (int kt = 0; kt < ID; kt += BK) {
        // ---- stage A (contiguous scratch rows; pad rows are zeros) ----
        {
            const float* hp = Hin + (size_t)(pbase + m0 + ar) * ID + kt + ak;
#pragma unroll
            for (int i = 0; i < 4; i++) {
                float4 v = *(const float4*)(hp + i * 4);
                int c = ak + i * 4;
                split_bf16(v.x, Ah[ar * APITCH + c + 0], Al[ar * APITCH + c + 0]);
                split_bf16(v.y, Ah[ar * APITCH + c + 1], Al[ar * APITCH + c + 1]);
                split_bf16(v.z, Ah[ar * APITCH + c + 2], Al[ar * APITCH + c + 2]);
                split_bf16(v.w, Ah[ar * APITCH + c + 3], Al[ar * APITCH + c + 3]);
            }
        }
        // ---- stage B ----
#pragma unroll
        for (int i = 0; i < 2; i++) {
            int idx = tid * 2 + i;
            int kr  = idx >> 4;
            int c4  = (idx & 15) * 4;
            float4 vb = *(const float4*)(wd + (size_t)(kt + kr) * HD + n0 + c4);
            split_bf16(vb.x, Bh[kr * BPITCH + c4 + 0], Bl[kr * BPITCH + c4 + 0]);
            split_bf16(vb.y, Bh[kr * BPITCH + c4 + 1], Bl[kr * BPITCH + c4 + 1]);
            split_bf16(vb.z, Bh[kr * BPITCH + c4 + 2], Bl[kr * BPITCH + c4 + 2]);
            split_bf16(vb.w, Bh[kr * BPITCH + c4 + 3], Bl[kr * BPITCH + c4 + 3]);
        }
        __syncthreads();

#pragma unroll
        for (int kk = 0; kk < BK; kk += 16) {
            wmma::fragment<wmma::matrix_a, 16, 16, 16, __nv_bfloat16, wmma::row_major> ah[2], al[2];
#pragma unroll
            for (int mi = 0; mi < 2; mi++) {
                wmma::load_matrix_sync(ah[mi], Ah + (wm0 + mi * 16) * APITCH + kk, APITCH);
                wmma::load_matrix_sync(al[mi], Al + (wm0 + mi * 16) * APITCH + kk, APITCH);
            }
            wmma::fragment<wmma::matrix_b, 16, 16, 16, __nv_bfloat16, wmma::row_major> bh[2], bl[2];
#pragma unroll
            for (int ni = 0; ni < 2; ni++) {
                wmma::load_matrix_sync(bh[ni], Bh + kk * BPITCH + wn0 + ni * 16, BPITCH);
                wmma::load_matrix_sync(bl[ni], Bl + kk * BPITCH + wn0 + ni * 16, BPITCH);
            }
#pragma unroll
            for (int mi = 0; mi < 2; mi++)
#pragma unroll
                for (int ni = 0; ni < 2; ni++) {
                    wmma::mma_sync(acc[mi][ni], ah[mi], bh[ni], acc[mi][ni]);
                    wmma::mma_sync(acc[mi][ni], ah[mi], bl[ni], acc[mi][ni]);
                    wmma::mma_sync(acc[mi][ni], al[mi], bh[ni], acc[mi][ni]);
                }
        }
        __syncthreads();
    }

    // epilogue: stage to smem, then guarded scatter (+= for routed)
#pragma unroll
    for (int mi = 0; mi < 2; mi++)
#pragma unroll
        for (int ni = 0; ni < 2; ni++)
            wmma::store_matrix_sync(Cs + (wm0 + mi * 16) * CPITCH + wn0 + ni * 16,
                                    acc[mi][ni], CPITCH, wmma::mem_row_major);
    __syncthreads();

#pragma unroll
    for (int it = 0; it < 8; it++) {
        int idx = tid + it * 256;       // 0..2047 float4s
        int row = idx >> 4;
        int c4  = (idx & 15) * 4;
        int gr  = m0 + row;
        if (gr < cnt) {
            int token = routed ? g_perm[obase + gr] : gr;
            float* po = out + (size_t)token * HD + n0 + c4;
            const float* ps = Cs + row * CPITCH + c4;
            float4 o = make_float4(ps[0], ps[1], ps[2], ps[3]);
            if (routed) {
                float4 prev = *(float4*)po;
                o.x += prev.x; o.y += prev.y; o.z += prev.z; o.w += prev.w;
            }
            *(float4*)po = o;
        }
    }
}

// ============================================================================
extern "C" void kernel_launch(void* const* d_in, const int* in_sizes, int n_in,
                              void* d_out, int out_size) {
    const float* x        = (const float*)d_in[0];
    const float* w_router = (const float*)d_in[1];
    const float* ws_gate  = (const float*)d_in[2];
    const float* ws_up    = (const float*)d_in[3];
    const float* ws_down  = (const float*)d_in[4];
    const float* we_gate  = (const float*)d_in[5];
    const float* we_up    = (const float*)d_in[6];
    const float* we_down  = (const float*)d_in[7];
    float* out = (float*)d_out;

    (void)in_sizes; (void)n_in; (void)out_size;

    router_kernel<<<T / 8, 256>>>(x, w_router);
    perm_kernel<<<1, T>>>();

    dim3 g1s(ID / BN, T / BM, 1);
    gateup_kernel<<<g1s, 256>>>(x, ws_gate, ws_up, 0);
    dim3 g1r(ID / BN, T / BM, E);
    gateup_kernel<<<g1r, 256>>>(x, we_gate, we_up, 1);

    dim3 g2s(HD / BN, T / BM, 1);
    down_kernel<<<g2s, 256>>>(ws_down, out, 0);
    dim3 g2r(HD / BN, T / BM, E);
    down_kernel<<<g2r, 256>>>(we_down, out, 1);
}

// round 5
// speedup vs baseline: 1.8774x; 1.8774x over previous
#include <cuda_runtime.h>
#include <cuda_bf16.h>
#include <cstdint>

#define T  1024
#define HD 2048
#define ID 4096
#define E  8

#define APITCH 40   // bf16 elems; 80B row pitch (conflict-free for ldmatrix)
#define BPITCH 72   // bf16 elems; 144B row pitch (conflict-free for ldmatrix)
#define NK1 (HD / 32)
#define NK2 (ID / 32)

// ---- scratch (static device globals; allocation-free) ----
__device__ __nv_bfloat16 g_x_hi[(size_t)T * HD];
__device__ __nv_bfloat16 g_x_lo[(size_t)T * HD];
__device__ __nv_bfloat16 g_xr_hi[(size_t)E * 1024 * HD];
__device__ __nv_bfloat16 g_xr_lo[(size_t)E * 1024 * HD];
__device__ __nv_bfloat16 g_hs_hi[(size_t)T * ID];
__device__ __nv_bfloat16 g_hs_lo[(size_t)T * ID];
__device__ __nv_bfloat16 g_hr_hi[(size_t)E * 1024 * ID];
__device__ __nv_bfloat16 g_hr_lo[(size_t)E * 1024 * ID];
__device__ int   g_expert[T];
__device__ float g_score[T];
__device__ int   g_perm[T];
__device__ int   g_offsets[E + 1];

// ---- helpers ----
__device__ __forceinline__ uint32_t smem_u32(const void* p) {
    uint32_t a;
    asm("{ .reg .u64 t; cvta.to.shared.u64 t, %1; cvt.u32.u64 %0, t; }" : "=r"(a) : "l"(p));
    return a;
}
__device__ __forceinline__ void ldsm4(uint32_t* r, uint32_t a) {
    asm volatile("ldmatrix.sync.aligned.m8n8.x4.shared.b16 {%0,%1,%2,%3}, [%4];"
                 : "=r"(r[0]), "=r"(r[1]), "=r"(r[2]), "=r"(r[3]) : "r"(a));
}
__device__ __forceinline__ void ldsm4t(uint32_t* r, uint32_t a) {
    asm volatile("ldmatrix.sync.aligned.m8n8.x4.trans.shared.b16 {%0,%1,%2,%3}, [%4];"
                 : "=r"(r[0]), "=r"(r[1]), "=r"(r[2]), "=r"(r[3]) : "r"(a));
}
__device__ __forceinline__ void mma_bf16(float* c, const uint32_t* a, const uint32_t* b) {
    asm volatile("mma.sync.aligned.m16n8k16.row.col.f32.bf16.bf16.f32 "
                 "{%0,%1,%2,%3}, {%4,%5,%6,%7}, {%8,%9}, {%0,%1,%2,%3};"
                 : "+f"(c[0]), "+f"(c[1]), "+f"(c[2]), "+f"(c[3])
                 : "r"(a[0]), "r"(a[1]), "r"(a[2]), "r"(a[3]), "r"(b[0]), "r"(b[1]));
}
__device__ __forceinline__ void split_bf16(float v, __nv_bfloat16& h, __nv_bfloat16& l) {
    h = __float2bfloat16_rn(v);
    l = __float2bfloat16_rn(v - __bfloat162float(h));
}
__device__ __forceinline__ uint32_t pack2(__nv_bfloat16 a, __nv_bfloat16 b) {
    __nv_bfloat162 t = __halves2bfloat162(a, b);
    return *(uint32_t*)&t;
}
// split 8 fp32 -> 8 bf16 hi (uint4) + 8 bf16 lo (uint4), stored to smem
__device__ __forceinline__ void split8(float4 v0, float4 v1,
                                       __nv_bfloat16* dh, __nv_bfloat16* dl) {
    float f[8] = {v0.x, v0.y, v0.z, v0.w, v1.x, v1.y, v1.z, v1.w};
    uint32_t H[4], L[4];
#pragma unroll
    for (int i = 0; i < 4; i++) {
        __nv_bfloat16 h0, l0, h1, l1;
        split_bf16(f[2*i], h0, l0);
        split_bf16(f[2*i+1], h1, l1);
        H[i] = pack2(h0, h1);
        L[i] = pack2(l0, l1);
    }
    *(uint4*)dh = make_uint4(H[0], H[1], H[2], H[3]);
    *(uint4*)dl = make_uint4(L[0], L[1], L[2], L[3]);
}

// ============================================================================
__global__ void router_kernel(const float* __restrict__ x, const float* __restrict__ wr) {
    int warp = (blockIdx.x * blockDim.x + threadIdx.x) >> 5;
    int lane = threadIdx.x & 31;
    if (warp >= T) return;
    const float* xr = x + (size_t)warp * HD;
    float acc[E];
#pragma unroll
    for (int e = 0; e < E; e++) acc[e] = 0.f;
    for (int h = lane; h < HD; h += 32) {
        float xv = xr[h];
        const float* w = wr + (size_t)h * E;
#pragma unroll
        for (int e = 0; e < E; e++) acc[e] += xv * w[e];
    }
#pragma unroll
    for (int e = 0; e < E; e++) {
#pragma unroll
        for (int o = 16; o; o >>= 1) acc[e] += __shfl_xor_sync(0xffffffffu, acc[e], o);
    }
    if (lane == 0) {
        int best = 0; float bv = acc[0];
#pragma unroll
        for (int e = 1; e < E; e++) if (acc[e] > bv) { bv = acc[e]; best = e; }
        g_expert[warp] = best;
        g_score[warp]  = 1.f / (1.f + __expf(-bv));
    }
}

__global__ void perm_kernel() {
    __shared__ int cnt[E], off[E + 1], cur[E];
    int t = threadIdx.x;
    if (t < E) cnt[t] = 0;
    __syncthreads();
    int e = g_expert[t];
    atomicAdd(&cnt[e], 1);
    __syncthreads();
    if (t == 0) {
        off[0] = 0;
        for (int i = 0; i < E; i++) off[i + 1] = off[i] + cnt[i];
    }
    __syncthreads();
    if (t < E) cur[t] = off[t];
    __syncthreads();
    int pos = atomicAdd(&cur[e], 1);
    g_perm[pos] = t;
    if (t <= E) g_offsets[t] = off[t];
}

__global__ void presplit_x(const float* __restrict__ x) {
    int idx = blockIdx.x * 256 + threadIdx.x;
    float4 v = *(const float4*)(x + (size_t)idx * 4);
    __nv_bfloat16 h0,l0,h1,l1,h2,l2,h3,l3;
    split_bf16(v.x,h0,l0); split_bf16(v.y,h1,l1); split_bf16(v.z,h2,l2); split_bf16(v.w,h3,l3);
    *(uint2*)(g_x_hi + (size_t)idx * 4) = make_uint2(pack2(h0,h1), pack2(h2,h3));
    *(uint2*)(g_x_lo + (size_t)idx * 4) = make_uint2(pack2(l0,l1), pack2(l2,l3));
}

// gather + scale + split routed A into per-expert groups (zero-padded to 256-mult)
__global__ void gather_kernel(const float* __restrict__ x) {
    int e = blockIdx.y;
    int obase = g_offsets[e], cnt = g_offsets[e + 1] - obase;
    int pad = (cnt + 255) & ~255;
    int r0 = blockIdx.x * 256;
    if (r0 >= pad) return;
    for (int idx = threadIdx.x; idx < 256 * HD / 4; idx += 256) {
        int row = idx >> 9;
        int c4  = (idx & 511) * 4;
        int r = r0 + row;
        uint2 hv = make_uint2(0u, 0u), lv = make_uint2(0u, 0u);
        if (r < cnt) {
            int tok = g_perm[obase + r];
            float sc = g_score[tok];
            float4 v = *(const float4*)(x + (size_t)tok * HD + c4);
            v.x *= sc; v.y *= sc; v.z *= sc; v.w *= sc;
            __nv_bfloat16 h0,l0,h1,l1,h2,l2,h3,l3;
            split_bf16(v.x,h0,l0); split_bf16(v.y,h1,l1); split_bf16(v.z,h2,l2); split_bf16(v.w,h3,l3);
            hv = make_uint2(pack2(h0,h1), pack2(h2,h3));
            lv = make_uint2(pack2(l0,l1), pack2(l2,l3));
        }
        size_t go = (size_t)(e * 1024 + r) * HD + c4;
        *(uint2*)(g_xr_hi + go) = hv;
        *(uint2*)(g_xr_lo + go) = lv;
    }
}

// ============================================================================
// GEMM1: h = silu(A@Wg) * (A@Wu).  BM=128, BN=64, BK=32; 8 warps (4m x 2n),
// warp tile 32x32 per matrix; split-bf16 3-term mma.sync.
// ============================================================================
__global__ __launch_bounds__(256)
void gateup_kernel(const float* __restrict__ Wg, const float* __restrict__ Wu, int routed) {
    __shared__ __nv_bfloat16 Ah[128 * APITCH], Al[128 * APITCH];
    __shared__ __nv_bfloat16 Bh[2][32 * BPITCH], Bl[2][32 * BPITCH];

    int tid = threadIdx.x, wid = tid >> 5, lane = tid & 31;

    int cnt; size_t arow0;
    const float *wg, *wu;
    const __nv_bfloat16 *axh, *axl;
    __nv_bfloat16 *ohh, *ohl;
    if (routed) {
        int e = blockIdx.z;
        cnt = g_offsets[e + 1] - g_offsets[e];
        wg = Wg + (size_t)e * HD * ID; wu = Wu + (size_t)e * HD * ID;
        axh = g_xr_hi; axl = g_xr_lo; ohh = g_hr_hi; ohl = g_hr_lo;
        arow0 = (size_t)e * 1024;
    } else {
        cnt = T; wg = Wg; wu = Wu;
        axh = g_x_hi; axl = g_x_lo; ohh = g_hs_hi; ohl = g_hs_lo;
        arow0 = 0;
    }
    int m0 = blockIdx.x * 128;
    if (m0 >= cnt) return;
    int n0 = blockIdx.y * 64;

    // staging indices
    int sa_row = tid >> 1, sa_col = (tid & 1) * 16;
    const __nv_bfloat16* pAh = axh + (arow0 + m0 + sa_row) * HD + sa_col;
    const __nv_bfloat16* pAl = axl + (arow0 + m0 + sa_row) * HD + sa_col;
    int sb_k = tid >> 3, sb_j = (tid & 7) * 8;
    const float* pG = wg + (size_t)sb_k * ID + n0 + sb_j;
    const float* pU = wu + (size_t)sb_k * ID + n0 + sb_j;
    int a_soff = sa_row * APITCH + sa_col;
    int b_soff = sb_k * BPITCH + sb_j;

    // MMA indices
    int wm = (wid >> 1) * 32, wn = (wid & 1) * 32;
    uint32_t sAh = smem_u32(Ah), sAl = smem_u32(Al);
    uint32_t sBh[2] = {smem_u32(Bh[0]), smem_u32(Bh[1])};
    uint32_t sBl[2] = {smem_u32(Bl[0]), smem_u32(Bl[1])};
    int a_lr = lane & 15, a_lc = (lane >> 4) * 8;
    int b_lk = (lane & 7) + (lane >> 4) * 8, b_ln = ((lane >> 3) & 1) * 8;

    float accg[2][4][4] = {}, accu[2][4][4] = {};

    uint4 a_h0, a_h1, a_l0, a_l1;
    float4 f_g0, f_g1, f_u0, f_u1;
#define GU_LDG(it) { \
    const __nv_bfloat16* ph = pAh + (it) * 32; \
    a_h0 = *(const uint4*)ph; a_h1 = *(const uint4*)(ph + 8); \
    const __nv_bfloat16* pl = pAl + (it) * 32; \
    a_l0 = *(const uint4*)pl; a_l1 = *(const uint4*)(pl + 8); \
    const float* pg = pG + (size_t)(it) * 32 * ID; \
    f_g0 = *(const float4*)pg; f_g1 = *(const float4*)(pg + 4); \
    const float* pu = pU + (size_t)(it) * 32 * ID; \
    f_u0 = *(const float4*)pu; f_u1 = *(const float4*)(pu + 4); }

    GU_LDG(0);
    for (int it = 0; it < NK1; it++) {
        *(uint4*)&Ah[a_soff] = a_h0; *(uint4*)&Ah[a_soff + 8] = a_h1;
        *(uint4*)&Al[a_soff] = a_l0; *(uint4*)&Al[a_soff + 8] = a_l1;
        split8(f_g0, f_g1, &Bh[0][b_soff], &Bl[0][b_soff]);
        split8(f_u0, f_u1, &Bh[1][b_soff], &Bl[1][b_soff]);
        if (it + 1 < NK1) GU_LDG(it + 1);
        __syncthreads();

#pragma unroll
        for (int kk = 0; kk < 32; kk += 16) {
            uint32_t ah[2][4], al2[2][4];
#pragma unroll
            for (int mi = 0; mi < 2; mi++) {
                uint32_t ao = (uint32_t)((wm + mi * 16 + a_lr) * APITCH + kk + a_lc) * 2;
                ldsm4(ah[mi], sAh + ao);
                ldsm4(al2[mi], sAl + ao);
            }
#pragma unroll
            for (int mat = 0; mat < 2; mat++) {
                uint32_t bh[4][2], bl2[4][2], r[4];
#pragma unroll
                for (int g2 = 0; g2 < 2; g2++) {
                    uint32_t bo = (uint32_t)((kk + b_lk) * BPITCH + wn + g2 * 16 + b_ln) * 2;
                    ldsm4t(r, sBh[mat] + bo);
                    bh[2*g2][0] = r[0]; bh[2*g2][1] = r[2];
                    bh[2*g2+1][0] = r[1]; bh[2*g2+1][1] = r[3];
                    ldsm4t(r, sBl[mat] + bo);
                    bl2[2*g2][0] = r[0]; bl2[2*g2][1] = r[2];
                    bl2[2*g2+1][0] = r[1]; bl2[2*g2+1][1] = r[3];
                }
                float (*acc)[4][4] = mat ? accu : accg;
#pragma unroll
                for (int mi = 0; mi < 2; mi++)
#pragma unroll
                    for (int ni = 0; ni < 4; ni++) {
                        mma_bf16(acc[mi][ni], ah[mi], bh[ni]);
                        mma_bf16(acc[mi][ni], ah[mi], bl2[ni]);
                        mma_bf16(acc[mi][ni], al2[mi], bh[ni]);
                    }
            }
        }
        __syncthreads();
    }
#undef GU_LDG

    // epilogue: h = silu(g)*u -> split bf16 (pad rows compute exact zeros)
    int er = lane >> 2, ec = (lane & 3) * 2;
#pragma unroll
    for (int mi = 0; mi < 2; mi++) {
#pragma unroll
        for (int half = 0; half < 2; half++) {
            size_t row = arow0 + m0 + wm + mi * 16 + er + half * 8;
#pragma unroll
            for (int ni = 0; ni < 4; ni++) {
                int c = n0 + wn + ni * 8 + ec;
                float g0 = accg[mi][ni][half*2],     u0 = accu[mi][ni][half*2];
                float g1 = accg[mi][ni][half*2 + 1], u1 = accu[mi][ni][half*2 + 1];
                float f0 = (g0 / (1.f + __expf(-g0))) * u0;
                float f1 = (g1 / (1.f + __expf(-g1))) * u1;
                __nv_bfloat16 h0, l0, h1, l1;
                split_bf16(f0, h0, l0); split_bf16(f1, h1, l1);
                *(uint32_t*)(ohh + row * ID + c) = pack2(h0, h1);
                *(uint32_t*)(ohl + row * ID + c) = pack2(l0, l1);
            }
        }
    }
}

// ============================================================================
// GEMM2: down projection. Same structure, one matrix. shared pass writes out,
// routed pass (stream-ordered after) does +=.
// ============================================================================
__global__ __launch_bounds__(256)
void down_kernel(const float* __restrict__ Wd, float* __restrict__ out, int routed) {
    __shared__ __nv_bfloat16 Ah[128 * APITCH], Al[128 * APITCH];
    __shared__ __nv_bfloat16 Bh[32 * BPITCH], Bl[32 * BPITCH];

    int tid = threadIdx.x, wid = tid >> 5, lane = tid & 31;

    int cnt, obase; size_t arow0;
    const float* wd;
    const __nv_bfloat16 *axh, *axl;
    if (routed) {
        int e = blockIdx.z;
        obase = g_offsets[e]; cnt = g_offsets[e + 1] - obase;
        wd = Wd + (size_t)e * ID * HD;
        axh = g_hr_hi; axl = g_hr_lo;
        arow0 = (size_t)e * 1024;
    } else {
        obase = 0; cnt = T; wd = Wd;
        axh = g_hs_hi; axl = g_hs_lo;
        arow0 = 0;
    }
    int m0 = blockIdx.x * 128;
    if (m0 >= cnt) return;
    int n0 = blockIdx.y * 64;

    int sa_row = tid >> 1, sa_col = (tid & 1) * 16;
    const __nv_bfloat16* pAh = axh + (arow0 + m0 + sa_row) * ID + sa_col;
    const __nv_bfloat16* pAl = axl + (arow0 + m0 + sa_row) * ID + sa_col;
    int sb_k = tid >> 3, sb_j = (tid & 7) * 8;
    const float* pW = wd + (size_t)sb_k * HD + n0 + sb_j;
    int a_soff = sa_row * APITCH + sa_col;
    int b_soff = sb_k * BPITCH + sb_j;

    int wm = (wid >> 1) * 32, wn = (wid & 1) * 32;
    uint32_t sAh = smem_u32(Ah), sAl = smem_u32(Al);
    uint32_t sBhs = smem_u32(Bh), sBls = smem_u32(Bl);
    int a_lr = lane & 15, a_lc = (lane >> 4) * 8;
    int b_lk = (lane & 7) + (lane >> 4) * 8, b_ln = ((lane >> 3) & 1) * 8;

    float acc[2][4][4] = {};

    uint4 a_h0, a_h1, a_l0, a_l1;
    float4 f_w0, f_w1;
#define DN_LDG(it) { \
    const __nv_bfloat16* ph = pAh + (it) * 32; \
    a_h0 = *(const uint4*)ph; a_h1 = *(const uint4*)(ph + 8); \
    const __nv_bfloat16* pl = pAl + (it) * 32; \
    a_l0 = *(const uint4*)pl; a_l1 = *(const uint4*)(pl + 8); \
    const float* pw = pW + (size_t)(it) * 32 * HD; \
    f_w0 = *(const float4*)pw; f_w1 = *(const float4*)(pw + 4); }

    DN_LDG(0);
    for (int it = 0; it < NK2; it++) {
        *(uint4*)&Ah[a_soff] = a_h0; *(uint4*)&Ah[a_soff + 8] = a_h1;
        *(uint4*)&Al[a_soff] = a_l0; *(uint4*)&Al[a_soff + 8] = a_l1;
        split8(f_w0, f_w1, &Bh[b_soff], &Bl[b_soff]);
        if (it + 1 < NK2) DN_LDG(it + 1);
        __syncthreads();

#pragma unroll
        for (int kk = 0; kk < 32; kk += 16) {
            uint32_t ah[2][4], al2[2][4];
#pragma unroll
            for (int mi = 0; mi < 2; mi++) {
                uint32_t ao = (uint32_t)((wm + mi * 16 + a_lr) * APITCH + kk + a_lc) * 2;
                ldsm4(ah[mi], sAh + ao);
                ldsm4(al2[mi], sAl + ao);
            }
            uint32_t bh[4][2], bl2[4][2], r[4];
#pragma unroll
            for (int g2 = 0; g2 < 2; g2++) {
                uint32_t bo = (uint32_t)((kk + b_lk) * BPITCH + wn + g2 * 16 + b_ln) * 2;
                ldsm4t(r, sBhs + bo);
                bh[2*g2][0] = r[0]; bh[2*g2][1] = r[2];
                bh[2*g2+1][0] = r[1]; bh[2*g2+1][1] = r[3];
                ldsm4t(r, sBls + bo);
                bl2[2*g2][0] = r[0]; bl2[2*g2][1] = r[2];
                bl2[2*g2+1][0] = r[1]; bl2[2*g2+1][1] = r[3];
            }
#pragma unroll
            for (int mi = 0; mi < 2; mi++)
#pragma unroll
                for (int ni = 0; ni < 4; ni++) {
                    mma_bf16(acc[mi][ni], ah[mi], bh[ni]);
                    mma_bf16(acc[mi][ni], ah[mi], bl2[ni]);
                    mma_bf16(acc[mi][ni], al2[mi], bh[ni]);
                }
        }
        __syncthreads();
    }
#undef DN_LDG

    // epilogue: scatter rows to out (write for shared, += for routed)
    int er = lane >> 2, ec = (lane & 3) * 2;
#pragma unroll
    for (int mi = 0; mi < 2; mi++) {
#pragma unroll
        for (int half = 0; half < 2; half++) {
            int gr = m0 + wm + mi * 16 + er + half * 8;
            int token = -1;
            if (gr < cnt) token = routed ? g_perm[obase + gr] : gr;
            if (token >= 0) {
#pragma unroll
                for (int ni = 0; ni < 4; ni++) {
                    int c = n0 + wn + ni * 8 + ec;
                    float2 v = make_float2(acc[mi][ni][half*2], acc[mi][ni][half*2 + 1]);
                    float2* p = (float2*)(out + (size_t)token * HD + c);
                    if (routed) { float2 o = *p; v.x += o.x; v.y += o.y; }
                    *p = v;
                }
            }
        }
    }
}

// ============================================================================
extern "C" void kernel_launch(void* const* d_in, const int* in_sizes, int n_in,
                              void* d_out, int out_size) {
    const float* x        = (const float*)d_in[0];
    const float* w_router = (const float*)d_in[1];
    const float* ws_gate  = (const float*)d_in[2];
    const float* ws_up    = (const float*)d_in[3];
    const float* ws_down  = (const float*)d_in[4];
    const float* we_gate  = (const float*)d_in[5];
    const float* we_up    = (const float*)d_in[6];
    const float* we_down  = (const float*)d_in[7];
    float* out = (float*)d_out;
    (void)in_sizes; (void)n_in; (void)out_size;

    router_kernel<<<T / 8, 256>>>(x, w_router);
    perm_kernel<<<1, T>>>();
    presplit_x<<<T * HD / 4 / 256, 256>>>(x);
    gather_kernel<<<dim3(4, E), 256>>>(x);

    gateup_kernel<<<dim3(T / 128, ID / 64, 1), 256>>>(ws_gate, ws_up, 0);
    gateup_kernel<<<dim3(T / 128, ID / 64, E), 256>>>(we_gate, we_up, 1);

    down_kernel<<<dim3(T / 128, HD / 64, 1), 256>>>(ws_down, out, 0);
    down_kernel<<<dim3(T / 128, HD / 64, E), 256>>>(we_down, out, 1);
}